// round 10
// baseline (speedup 1.0000x reference)
#include <cuda_runtime.h>
#include <cstdint>

// Problem constants
#define BB 8
#define TT 128
#define S_ENC 400
#define HH 256
#define VV 50257

#define TABLE 1024
#define TMASK (TABLE - 1)
#define NWORDS ((VV + 31) / 32)   // 1571 bitmap words
#define THREADS 256
#define NWARPS (THREADS / 32)

__device__ __forceinline__ unsigned hash_tok(unsigned t) {
    return (t * 2654435761u) & TMASK;
}

__global__ void __launch_bounds__(THREADS, 4)
pointer_gen_fused(const int*   __restrict__ tokens,   // [B, S]
                  const float* __restrict__ ctx,      // [B, T, H]
                  const float* __restrict__ dec_in,   // [B, T, H]
                  const float* __restrict__ dec_out,  // [B, T, H]
                  const float* __restrict__ vocab,    // [B, T, V]
                  const float* __restrict__ attn,     // [B, T, S]
                  const float* __restrict__ Wc, const float* __restrict__ bc,
                  const float* __restrict__ Wo, const float* __restrict__ bo,
                  const float* __restrict__ Wi, const float* __restrict__ bi,
                  float*       __restrict__ out)      // [B, T, V]
{
    __shared__ int      keys[TABLE];
    __shared__ float    vals[TABLE];
    __shared__ unsigned bitmap[NWORDS];
    __shared__ float    red[NWARPS];
    __shared__ float    s_pg, s_lse;
    __shared__ int      s_nd;

    const int row  = blockIdx.x;          // b*T + t
    const int b    = row / TT;
    const int tid  = threadIdx.x;
    const int lane = tid & 31;
    const int warp = tid >> 5;

    // ---- init shared ----
    #pragma unroll
    for (int i = tid; i < TABLE; i += THREADS) { keys[i] = -1; vals[i] = 0.f; }
    for (int i = tid; i < NWORDS; i += THREADS) bitmap[i] = 0u;
    if (tid == 0) s_nd = 0;

    // ---- p_gen partial dot (H == THREADS) ----
    const float* cr  = ctx     + (size_t)row * HH;
    const float* dir = dec_in  + (size_t)row * HH;
    const float* dor = dec_out + (size_t)row * HH;
    float p = cr[tid] * Wc[tid] + dor[tid] * Wo[tid] + dir[tid] * Wi[tid];
    #pragma unroll
    for (int o = 16; o; o >>= 1) p += __shfl_down_sync(0xffffffffu, p, o);

    __syncthreads();                      // shared init complete
    if (lane == 0) red[warp] = p;
    __syncthreads();
    if (tid == 0) {
        float s = bc[0] + bo[0] + bi[0];
        #pragma unroll
        for (int w = 0; w < NWARPS; w++) s += red[w];
        s_pg = 1.f / (1.f + __expf(-s));
    }

    // ---- scatter attn into hash table (dedup + accumulate) ----
    const int*   tokb = tokens + b * S_ENC;
    const float* ar   = attn + (size_t)row * S_ENC;
    for (int s = tid; s < S_ENC; s += THREADS) {
        int   tok = tokb[s];
        float a   = ar[s];
        unsigned slot = hash_tok((unsigned)tok);
        while (true) {
            int prev = atomicCAS(&keys[slot], -1, tok);
            if (prev == -1 || prev == tok) {
                atomicAdd(&vals[slot], a);
                if (prev == -1) {
                    atomicAdd(&s_nd, 1);
                    atomicOr(&bitmap[tok >> 5], 1u << (tok & 31));
                }
                break;
            }
            slot = (slot + 1) & TMASK;
        }
    }
    __syncthreads();

    // ---- ONE-pass lse: vals small (sums of uniforms), exp can't overflow
    float se = 0.f;
    #pragma unroll
    for (int i = tid; i < TABLE; i += THREADS)
        if (keys[i] != -1) se += __expf(vals[i]);
    #pragma unroll
    for (int o = 16; o; o >>= 1) se += __shfl_down_sync(0xffffffffu, se, o);
    if (lane == 0) red[warp] = se;
    __syncthreads();
    if (tid == 0) {
        float s = 0.f;
        #pragma unroll
        for (int w = 0; w < NWARPS; w++) s += red[w];
        s_lse = __logf(s + (float)(VV - s_nd));
    }
    __syncthreads();

    const float pg    = s_pg;
    const float one_m = 1.f - pg;
    const float base  = -one_m * s_lse;  // out = vocab*pg + one_m*copy + base

    const float* vr   = vocab + (size_t)row * VV;
    float*       orow = out   + (size_t)row * VV;

    // ---- streaming pass: alignment peel (V odd -> row base alternates) ----
    int head = (int)((4 - (((size_t)row * VV) & 3)) & 3);
    for (int v = tid; v < head; v += THREADS) {
        float c = 0.f;
        if ((bitmap[v >> 5] >> (v & 31)) & 1u) {
            unsigned slot = hash_tok((unsigned)v);
            while (keys[slot] != v) slot = (slot + 1) & TMASK;
            c = vals[slot];
        }
        orow[v] = vr[v] * pg + one_m * c + base;
    }

    const int n4 = (VV - head) >> 2;
    const float4* vr4 = (const float4*)(vr + head);
    float4*       or4 = (float4*)(orow + head);

    // pairwise-unrolled main loop: two independent LDG.128 per iteration,
    // fixup structure identical to R5's proven per-element form
    int i = tid;
    for (; i + THREADS < n4; i += 2 * THREADS) {
        float4 x0 = vr4[i];
        float4 x1 = vr4[i + THREADS];

        int vb0 = head + i * 4;
        float c0[4] = {0.f, 0.f, 0.f, 0.f};
        #pragma unroll
        for (int k = 0; k < 4; k++) {
            int v = vb0 + k;
            if ((bitmap[v >> 5] >> (v & 31)) & 1u) {
                unsigned slot = hash_tok((unsigned)v);
                while (keys[slot] != v) slot = (slot + 1) & TMASK;
                c0[k] = vals[slot];
            }
        }
        int vb1 = head + (i + THREADS) * 4;
        float c1[4] = {0.f, 0.f, 0.f, 0.f};
        #pragma unroll
        for (int k = 0; k < 4; k++) {
            int v = vb1 + k;
            if ((bitmap[v >> 5] >> (v & 31)) & 1u) {
                unsigned slot = hash_tok((unsigned)v);
                while (keys[slot] != v) slot = (slot + 1) & TMASK;
                c1[k] = vals[slot];
            }
        }
        float4 y0, y1;
        y0.x = x0.x * pg + one_m * c0[0] + base;
        y0.y = x0.y * pg + one_m * c0[1] + base;
        y0.z = x0.z * pg + one_m * c0[2] + base;
        y0.w = x0.w * pg + one_m * c0[3] + base;
        y1.x = x1.x * pg + one_m * c1[0] + base;
        y1.y = x1.y * pg + one_m * c1[1] + base;
        y1.z = x1.z * pg + one_m * c1[2] + base;
        y1.w = x1.w * pg + one_m * c1[3] + base;
        or4[i]           = y0;
        or4[i + THREADS] = y1;
    }
    for (; i < n4; i += THREADS) {
        float4 x = vr4[i];
        int vb = head + i * 4;
        float c[4] = {0.f, 0.f, 0.f, 0.f};
        #pragma unroll
        for (int k = 0; k < 4; k++) {
            int v = vb + k;
            if ((bitmap[v >> 5] >> (v & 31)) & 1u) {
                unsigned slot = hash_tok((unsigned)v);
                while (keys[slot] != v) slot = (slot + 1) & TMASK;
                c[k] = vals[slot];
            }
        }
        float4 y;
        y.x = x.x * pg + one_m * c[0] + base;
        y.y = x.y * pg + one_m * c[1] + base;
        y.z = x.z * pg + one_m * c[2] + base;
        y.w = x.w * pg + one_m * c[3] + base;
        or4[i] = y;
    }

    for (int v = head + n4 * 4 + tid; v < VV; v += THREADS) {
        float c = 0.f;
        if ((bitmap[v >> 5] >> (v & 31)) & 1u) {
            unsigned slot = hash_tok((unsigned)v);
            while (keys[slot] != v) slot = (slot + 1) & TMASK;
            c = vals[slot];
        }
        orow[v] = vr[v] * pg + one_m * c + base;
    }
}

extern "C" void kernel_launch(void* const* d_in, const int* in_sizes, int n_in,
                              void* d_out, int out_size)
{
    // metadata order (setup_inputs dict order):
    // 0 input_tokens [B,S] int32
    // 1 context [B,T,H]  2 decoder_input  3 decoder_output
    // 4 vocab_dist [B,T,V]  5 attn_dist [B,T,S]  6 encoder_outputs (unused)
    // 7 Wc  8 bc  9 Wo  10 bo  11 Wi  12 bi
    const int*   tokens  = (const int*)  d_in[0];
    const float* ctx     = (const float*)d_in[1];
    const float* dec_in  = (const float*)d_in[2];
    const float* dec_out = (const float*)d_in[3];
    const float* vocab   = (const float*)d_in[4];
    const float* attn    = (const float*)d_in[5];
    const float* Wc      = (const float*)d_in[7];
    const float* bc      = (const float*)d_in[8];
    const float* Wo      = (const float*)d_in[9];
    const float* bo      = (const float*)d_in[10];
    const float* Wi      = (const float*)d_in[11];
    const float* bi      = (const float*)d_in[12];
    float* out = (float*)d_out;

    pointer_gen_fused<<<BB * TT, THREADS>>>(tokens, ctx, dec_in, dec_out, vocab,
                                            attn, Wc, bc, Wo, bo, Wi, bi, out);
}

// round 11
// speedup vs baseline: 1.1192x; 1.1192x over previous
#include <cuda_runtime.h>
#include <cstdint>

// Problem constants
#define BB 8
#define TT 128
#define S_ENC 400
#define HH 256
#define VV 50257

#define TABLE 1024
#define TMASK (TABLE - 1)
#define NWORDS ((VV + 31) / 32)   // 1571 bitmap words
#define THREADS 512
#define NWARPS (THREADS / 32)

__device__ __forceinline__ unsigned hash_tok(unsigned t) {
    return (t * 2654435761u) & TMASK;
}

__global__ void __launch_bounds__(THREADS, 2)
pointer_gen_fused(const int*   __restrict__ tokens,   // [B, S]
                  const float* __restrict__ ctx,      // [B, T, H]
                  const float* __restrict__ dec_in,   // [B, T, H]
                  const float* __restrict__ dec_out,  // [B, T, H]
                  const float* __restrict__ vocab,    // [B, T, V]
                  const float* __restrict__ attn,     // [B, T, S]
                  const float* __restrict__ Wc, const float* __restrict__ bc,
                  const float* __restrict__ Wo, const float* __restrict__ bo,
                  const float* __restrict__ Wi, const float* __restrict__ bi,
                  float*       __restrict__ out)      // [B, T, V]
{
    __shared__ int      keys[TABLE];
    __shared__ float    vals[TABLE];
    __shared__ unsigned bitmap[NWORDS];
    __shared__ float    red[NWARPS];
    __shared__ float    s_pg, s_lse;
    __shared__ int      s_nd;

    const int row  = blockIdx.x;          // b*T + t
    const int b    = row / TT;
    const int tid  = threadIdx.x;
    const int lane = tid & 31;
    const int warp = tid >> 5;

    // ---- init shared ----
    #pragma unroll
    for (int i = tid; i < TABLE; i += THREADS) { keys[i] = -1; vals[i] = 0.f; }
    for (int i = tid; i < NWORDS; i += THREADS) bitmap[i] = 0u;
    if (tid == 0) s_nd = 0;

    // ---- p_gen partial dot (H = 256 < THREADS: guard) ----
    float p = 0.f;
    if (tid < HH) {
        p = ctx[(size_t)row * HH + tid]     * Wc[tid]
          + dec_out[(size_t)row * HH + tid] * Wo[tid]
          + dec_in[(size_t)row * HH + tid]  * Wi[tid];
    }
    #pragma unroll
    for (int o = 16; o; o >>= 1) p += __shfl_down_sync(0xffffffffu, p, o);

    __syncthreads();                      // shared init complete
    if (lane == 0) red[warp] = p;
    __syncthreads();
    if (tid == 0) {
        float s = bc[0] + bo[0] + bi[0];
        #pragma unroll
        for (int w = 0; w < NWARPS; w++) s += red[w];
        s_pg = 1.f / (1.f + __expf(-s));
    }

    // ---- scatter attn into hash table (dedup + accumulate) ----
    const int*   tokb = tokens + b * S_ENC;
    const float* ar   = attn + (size_t)row * S_ENC;
    for (int s = tid; s < S_ENC; s += THREADS) {
        int   tok = tokb[s];
        float a   = ar[s];
        unsigned slot = hash_tok((unsigned)tok);
        while (true) {
            int prev = atomicCAS(&keys[slot], -1, tok);
            if (prev == -1 || prev == tok) {
                atomicAdd(&vals[slot], a);
                if (prev == -1) {
                    atomicAdd(&s_nd, 1);
                    atomicOr(&bitmap[tok >> 5], 1u << (tok & 31));
                }
                break;
            }
            slot = (slot + 1) & TMASK;
        }
    }
    __syncthreads();

    // ---- ONE-pass lse: vals small (sums of uniforms), exp can't overflow
    float se = 0.f;
    #pragma unroll
    for (int i = tid; i < TABLE; i += THREADS)
        if (keys[i] != -1) se += __expf(vals[i]);
    #pragma unroll
    for (int o = 16; o; o >>= 1) se += __shfl_down_sync(0xffffffffu, se, o);
    if (lane == 0) red[warp] = se;
    __syncthreads();
    if (tid == 0) {
        float s = 0.f;
        #pragma unroll
        for (int w = 0; w < NWARPS; w++) s += red[w];
        s_lse = __logf(s + (float)(VV - s_nd));
    }
    __syncthreads();

    const float pg    = s_pg;
    const float one_m = 1.f - pg;
    const float base  = -one_m * s_lse;  // out = vocab*pg + one_m*copy + base

    const float* vr   = vocab + (size_t)row * VV;
    float*       orow = out   + (size_t)row * VV;

    // ---- streaming pass: alignment peel (V odd -> row base alternates) ----
    int head = (int)((4 - (((size_t)row * VV) & 3)) & 3);
    for (int v = tid; v < head; v += THREADS) {
        float c = 0.f;
        if ((bitmap[v >> 5] >> (v & 31)) & 1u) {
            unsigned slot = hash_tok((unsigned)v);
            while (keys[slot] != v) slot = (slot + 1) & TMASK;
            c = vals[slot];
        }
        orow[v] = vr[v] * pg + one_m * c + base;
    }

    const int n4 = (VV - head) >> 2;
    const float4* vr4 = (const float4*)(vr + head);
    float4*       or4 = (float4*)(orow + head);
    for (int i = tid; i < n4; i += THREADS) {
        float4 x = vr4[i];
        int vb = head + i * 4;
        float c[4] = {0.f, 0.f, 0.f, 0.f};
        #pragma unroll
        for (int k = 0; k < 4; k++) {
            int v = vb + k;
            if ((bitmap[v >> 5] >> (v & 31)) & 1u) {
                unsigned slot = hash_tok((unsigned)v);
                while (keys[slot] != v) slot = (slot + 1) & TMASK;
                c[k] = vals[slot];
            }
        }
        float4 y;
        y.x = x.x * pg + one_m * c[0] + base;
        y.y = x.y * pg + one_m * c[1] + base;
        y.z = x.z * pg + one_m * c[2] + base;
        y.w = x.w * pg + one_m * c[3] + base;
        or4[i] = y;
    }

    for (int v = head + n4 * 4 + tid; v < VV; v += THREADS) {
        float c = 0.f;
        if ((bitmap[v >> 5] >> (v & 31)) & 1u) {
            unsigned slot = hash_tok((unsigned)v);
            while (keys[slot] != v) slot = (slot + 1) & TMASK;
            c = vals[slot];
        }
        orow[v] = vr[v] * pg + one_m * c + base;
    }
}

extern "C" void kernel_launch(void* const* d_in, const int* in_sizes, int n_in,
                              void* d_out, int out_size)
{
    // metadata order (setup_inputs dict order):
    // 0 input_tokens [B,S] int32
    // 1 context [B,T,H]  2 decoder_input  3 decoder_output
    // 4 vocab_dist [B,T,V]  5 attn_dist [B,T,S]  6 encoder_outputs (unused)
    // 7 Wc  8 bc  9 Wo  10 bo  11 Wi  12 bi
    const int*   tokens  = (const int*)  d_in[0];
    const float* ctx     = (const float*)d_in[1];
    const float* dec_in  = (const float*)d_in[2];
    const float* dec_out = (const float*)d_in[3];
    const float* vocab   = (const float*)d_in[4];
    const float* attn    = (const float*)d_in[5];
    const float* Wc      = (const float*)d_in[7];
    const float* bc      = (const float*)d_in[8];
    const float* Wo      = (const float*)d_in[9];
    const float* bo      = (const float*)d_in[10];
    const float* Wi      = (const float*)d_in[11];
    const float* bi      = (const float*)d_in[12];
    float* out = (float*)d_out;

    pointer_gen_fused<<<BB * TT, THREADS>>>(tokens, ctx, dec_in, dec_out, vocab,
                                            attn, Wc, bc, Wo, bo, Wi, bi, out);
}